// round 5
// baseline (speedup 1.0000x reference)
#include <cuda_runtime.h>
#include <cuda_bf16.h>

// ---------------------------------------------------------------------------
// IngredientPositionEncoding, fused single kernel (fast path D%4==0):
//   Block = 512 threads = 16 warps, owns 16 consecutive output rows.
//   Phase A: block scans its batch row's separator mask (warp-shuffle scan),
//            captures the <=17 separator positions bounding its 16 segments,
//            builds (flat_start, cnt, s) meta in shared.
//   Phase B: warp w streams row base+w: contiguous cnt x D slab, float4
//            loads, 5-deep unroll, mean + pe, coalesced store.
// The 16 blocks sharing one batch row hit L2 for the (small) mask re-scan;
// this removes the separate boundary kernel + meta round-trip + launch gap.
// ---------------------------------------------------------------------------

#define ROWS_PER_BLOCK 16
#define THREADS 512
#define NWARPS (THREADS / 32)
#define MAX_OUT_ROWS 65536

__device__ int4 g_seg_meta[MAX_OUT_ROWS];   // only used by fallback path
__device__ int  g_fallback_max_ingr = 256;

// ---------------------------------------------------------------------------
// Fused kernel
// ---------------------------------------------------------------------------
__global__ void __launch_bounds__(THREADS, 3)
seg_mean_fused_kernel(const float4* __restrict__ x4,
                      const float4* __restrict__ pe4,
                      const int* __restrict__ mask,
                      const int* __restrict__ max_ingr_ptr,
                      float4* __restrict__ out4,
                      int D4, int OUT_ROWS, int BL)
{
    __shared__ int4 sh_meta[ROWS_PER_BLOCK];     // (flat_start, cnt, s, 0)
    __shared__ int  sh_pos[ROWS_PER_BLOCK + 2];  // separator-position window
    __shared__ int  sh_warp[NWARPS + 1];

    const int max_ingr = *max_ingr_ptr;
    const int B = OUT_ROWS / max_ingr;
    const int L = BL / B;

    const int base  = blockIdx.x * ROWS_PER_BLOCK;
    if (base >= OUT_ROWS) return;
    const int nrows = min(ROWS_PER_BLOCK, OUT_ROWS - base);

    const int tid  = threadIdx.x;
    const int lane = tid & 31;
    const int wid  = tid >> 5;

    // ---- Phase A: boundary scan for each distinct batch row in this block --
    const int b_first = base / max_ingr;
    const int b_last  = (base + nrows - 1) / max_ingr;

    for (int bb = b_first; bb <= b_last; ++bb) {
        const int r_lo = max(base, bb * max_ingr);
        const int r_hi = min(base + nrows - 1, (bb + 1) * max_ingr - 1);
        const int s_lo = r_lo - bb * max_ingr;
        const int s_hi = r_hi - bb * max_ingr;
        const int W_lo = s_lo - 1;               // may be -1 (unused slot 0)

        const int* mrow = mask + (long long)bb * L;
        const int chunk = (L + THREADS - 1) / THREADS;
        const int beg = tid * chunk;
        const int end = min(beg + chunk, L);

        // per-thread separator count (int4 fast path)
        int c = 0;
        if (((chunk & 3) == 0) && ((L & 3) == 0) && (beg < end)) {
            const int4* m4 = (const int4*)(mrow + beg);
            const int n4 = (end - beg) >> 2;
            for (int i = 0; i < n4; ++i) {
                int4 v = m4[i];
                c += (v.x != 0) + (v.y != 0) + (v.z != 0) + (v.w != 0);
            }
        } else {
            for (int i = beg; i < end; ++i) c += (mrow[i] != 0);
        }

        // warp inclusive scan
        int inc = c;
        #pragma unroll
        for (int o = 1; o < 32; o <<= 1) {
            int v = __shfl_up_sync(0xffffffffu, inc, o);
            if (lane >= o) inc += v;
        }
        if (lane == 31) sh_warp[wid] = inc;
        __syncthreads();

        if (tid == 0) {
            int acc = 0;
            #pragma unroll
            for (int w = 0; w < NWARPS; ++w) {
                int t = sh_warp[w]; sh_warp[w] = acc; acc += t;
            }
            sh_warp[NWARPS] = acc;
        }
        __syncthreads();

        const int excl = inc - c + sh_warp[wid];
        const int nsep = sh_warp[NWARPS];

        // scatter: keep only separator positions with ordinal in [W_lo, s_hi+1]
        {
            int j = excl;
            if (j <= s_hi + 1) {                 // skip threads past window
                for (int i = beg; i < end; ++i) {
                    if (mrow[i] != 0) {
                        if (j >= W_lo && j <= s_hi + 1)
                            sh_pos[j - W_lo] = i;
                        ++j;
                        if (j > s_hi + 1) break;
                    }
                }
            }
        }
        __syncthreads();

        // build meta for this bb's rows (one thread per row)
        const int i0 = r_lo - base;
        const int cnt_rows = r_hi - r_lo + 1;
        if (tid < cnt_rows) {
            const int s = s_lo + tid;
            int start, cnt;
            if (s < nsep) {
                start = (s == 0) ? 0 : (sh_pos[s - W_lo - 1] + 1);
                cnt   = sh_pos[s - W_lo] - start;
            } else if (s == nsep) {
                start = (nsep == 0) ? 0 : (sh_pos[nsep - W_lo - 1] + 1);
                cnt   = L - start;
            } else {
                start = 0; cnt = 0;
            }
            int4 m;
            m.x = bb * L + start;
            m.y = cnt;
            m.z = s;
            m.w = 0;
            sh_meta[i0 + tid] = m;
        }
        __syncthreads();
    }

    // ---- Phase B: one warp per row, stream + mean + pe ---------------------
    if (wid >= nrows) return;
    const int r = base + wid;
    const int4 md = sh_meta[wid];
    const int start = md.x;
    const int cnt   = md.y;
    const int s     = md.z;

    const float4* __restrict__ xp = x4 + (long long)start * D4;
    const float inv = (cnt > 0) ? (1.0f / (float)cnt) : 0.0f;

    for (int c = lane; c < D4; c += 32) {
        float4 a0 = {0.f,0.f,0.f,0.f}, a1 = a0, a2 = a0, a3 = a0, a4 = a0;
        int t = 0;
        // 5-deep unroll: cnt=15 -> exactly 3 iterations, no tail
        for (; t + 5 <= cnt; t += 5) {
            float4 v0 = xp[(long long)(t + 0) * D4 + c];
            float4 v1 = xp[(long long)(t + 1) * D4 + c];
            float4 v2 = xp[(long long)(t + 2) * D4 + c];
            float4 v3 = xp[(long long)(t + 3) * D4 + c];
            float4 v4 = xp[(long long)(t + 4) * D4 + c];
            a0.x += v0.x; a0.y += v0.y; a0.z += v0.z; a0.w += v0.w;
            a1.x += v1.x; a1.y += v1.y; a1.z += v1.z; a1.w += v1.w;
            a2.x += v2.x; a2.y += v2.y; a2.z += v2.z; a2.w += v2.w;
            a3.x += v3.x; a3.y += v3.y; a3.z += v3.z; a3.w += v3.w;
            a4.x += v4.x; a4.y += v4.y; a4.z += v4.z; a4.w += v4.w;
        }
        for (; t < cnt; ++t) {
            float4 v = xp[(long long)t * D4 + c];
            a0.x += v.x; a0.y += v.y; a0.z += v.z; a0.w += v.w;
        }
        float4 sum;
        sum.x = ((a0.x + a1.x) + (a2.x + a3.x)) + a4.x;
        sum.y = ((a0.y + a1.y) + (a2.y + a3.y)) + a4.y;
        sum.z = ((a0.z + a1.z) + (a2.z + a3.z)) + a4.z;
        sum.w = ((a0.w + a1.w) + (a2.w + a3.w)) + a4.w;

        float4 p = pe4[(long long)s * D4 + c];
        float4 o;
        o.x = sum.x * inv + p.x;
        o.y = sum.y * inv + p.y;
        o.z = sum.z * inv + p.z;
        o.w = sum.w * inv + p.w;
        out4[(long long)r * D4 + c] = o;
    }
}

// ---------------------------------------------------------------------------
// Fallback path (any D): boundary kernel + scalar mean kernel (as before).
// ---------------------------------------------------------------------------
__global__ void __launch_bounds__(256)
seg_bounds_kernel(const int* __restrict__ mask,
                  const int* __restrict__ max_ingr_ptr,
                  int BL, int OUT_ROWS,
                  int4* __restrict__ meta)
{
    const int max_ingr = *max_ingr_ptr;
    const int B = OUT_ROWS / max_ingr;
    const int L = BL / B;

    __shared__ int sh_sep[4096];
    __shared__ int sh_warp[9];

    const int tid  = threadIdx.x;
    const int lane = tid & 31;
    const int wid  = tid >> 5;
    const int nthr = blockDim.x;

    for (int b = blockIdx.x; b < B; b += gridDim.x) {
        const int* mrow = mask + (long long)b * L;
        const int chunk = (L + nthr - 1) / nthr;
        const int beg = tid * chunk;
        const int end = min(beg + chunk, L);

        int c = 0;
        for (int i = beg; i < end; ++i) c += (mrow[i] != 0);

        int inc = c;
        #pragma unroll
        for (int o = 1; o < 32; o <<= 1) {
            int v = __shfl_up_sync(0xffffffffu, inc, o);
            if (lane >= o) inc += v;
        }
        if (lane == 31) sh_warp[wid] = inc;
        __syncthreads();
        if (tid == 0) {
            int acc = 0;
            #pragma unroll
            for (int w = 0; w < 8; ++w) { int t = sh_warp[w]; sh_warp[w] = acc; acc += t; }
            sh_warp[8] = acc;
        }
        __syncthreads();
        const int excl = inc - c + sh_warp[wid];
        const int nsep = sh_warp[8];
        int j = excl;
        for (int i = beg; i < end; ++i) {
            if (mrow[i] != 0) { if (j < 4096) sh_sep[j] = i; ++j; }
        }
        __syncthreads();
        for (int s = tid; s < max_ingr; s += nthr) {
            int start, cnt;
            if (s < nsep) {
                start = (s == 0) ? 0 : (sh_sep[s - 1] + 1);
                cnt   = sh_sep[s] - start;
            } else if (s == nsep) {
                start = (nsep == 0) ? 0 : (sh_sep[nsep - 1] + 1);
                cnt   = L - start;
            } else { start = 0; cnt = 0; }
            meta[b * max_ingr + s] = make_int4(b * L + start, cnt, s, 0);
        }
        __syncthreads();
    }
}

__global__ void seg_mean_scalar_kernel(const float* __restrict__ x,
                                       const float* __restrict__ pe,
                                       const int4* __restrict__ meta,
                                       float* __restrict__ out,
                                       int D)
{
    const int r = blockIdx.x;
    const int4 md = meta[r];
    const int start = md.x;
    const int cnt   = md.y;
    const int s     = md.z;
    const float inv = (cnt > 0) ? (1.0f / (float)cnt) : 0.0f;

    for (int d = threadIdx.x; d < D; d += blockDim.x) {
        const float* xp = x + (long long)start * D + d;
        float a0 = 0.f, a1 = 0.f, a2 = 0.f, a3 = 0.f;
        int t = 0;
        for (; t + 4 <= cnt; t += 4) {
            a0 += xp[(long long)(t + 0) * D];
            a1 += xp[(long long)(t + 1) * D];
            a2 += xp[(long long)(t + 2) * D];
            a3 += xp[(long long)(t + 3) * D];
        }
        for (; t < cnt; ++t) a0 += xp[(long long)t * D];
        float sum = (a0 + a1) + (a2 + a3);
        out[(long long)r * D + d] = sum * inv + pe[(long long)s * D + d];
    }
}

// ---------------------------------------------------------------------------
// Launch
// ---------------------------------------------------------------------------
extern "C" void kernel_launch(void* const* d_in, const int* in_sizes, int n_in,
                              void* d_out, int out_size)
{
    const float* x    = (const float*)d_in[0];
    const int*   mask = (const int*)d_in[1];
    const float* pe   = (const float*)d_in[2];

    const int* max_ingr_ptr;
    if (n_in >= 4) {
        max_ingr_ptr = (const int*)d_in[3];
    } else {
        int* p = nullptr;
        cudaGetSymbolAddress((void**)&p, g_fallback_max_ingr);
        max_ingr_ptr = p;
    }

    const int x_size    = in_sizes[0];            // B*L*D
    const int mask_size = in_sizes[1];            // B*L
    const int D         = x_size / mask_size;     // 128
    const int OUT_ROWS  = out_size / D;           // B*max_ingr

    if ((D & 3) == 0) {
        const int D4 = D >> 2;
        const int grid = (OUT_ROWS + ROWS_PER_BLOCK - 1) / ROWS_PER_BLOCK;
        seg_mean_fused_kernel<<<grid, THREADS>>>(
            (const float4*)x, (const float4*)pe, mask, max_ingr_ptr,
            (float4*)d_out, D4, OUT_ROWS, mask_size);
    } else {
        int4* meta_p = nullptr;
        cudaGetSymbolAddress((void**)&meta_p, g_seg_meta);
        seg_bounds_kernel<<<256, 256>>>(mask, max_ingr_ptr,
                                        mask_size, OUT_ROWS, meta_p);
        seg_mean_scalar_kernel<<<OUT_ROWS, 128>>>(
            x, pe, meta_p, (float*)d_out, D);
    }
}

// round 6
// speedup vs baseline: 1.1279x; 1.1279x over previous
#include <cuda_runtime.h>
#include <cuda_bf16.h>

// ---------------------------------------------------------------------------
// IngredientPositionEncoding: segment-mean pooling + positional encoding.
//
// Kernel 1 (grid-stride over batch rows): warp-shuffle scan of separator
//   mask (int4 reads), emit packed int4 meta per output row:
//   (flat_start_token, count, segment_index, 0).
// Kernel 2: 8 warps/block, one output row per warp, float4 loads 5-deep with
//   a SINGLE accumulator (low reg pressure), __launch_bounds__(256,6) to get
//   6 blocks/SM (75% occupancy) — the streaming phase is warp-count-bound.
// ---------------------------------------------------------------------------

#define MAX_SEPS_CAP 4096       // >= L
#define MAX_OUT_ROWS 65536      // >= B*max_ingr
#define ROWS_PER_BLOCK 8

__device__ int4 g_seg_meta[MAX_OUT_ROWS];   // (flat_start, cnt, s, 0)
__device__ int  g_fallback_max_ingr = 256;

// ---------------------------------------------------------------------------
// Kernel 1: segment boundaries. Grid-stride over batch rows.
// ---------------------------------------------------------------------------
__global__ void __launch_bounds__(256)
seg_bounds_kernel(const int* __restrict__ mask,
                  const int* __restrict__ max_ingr_ptr,
                  int BL, int OUT_ROWS,
                  int4* __restrict__ meta)
{
    const int max_ingr = *max_ingr_ptr;
    const int B = OUT_ROWS / max_ingr;
    const int L = BL / B;

    __shared__ int sh_sep[MAX_SEPS_CAP];
    __shared__ int sh_warp[9];

    const int tid  = threadIdx.x;
    const int lane = tid & 31;
    const int wid  = tid >> 5;
    const int nthr = blockDim.x;

    for (int b = blockIdx.x; b < B; b += gridDim.x) {
        const int* mrow = mask + b * L;
        const int chunk = (L + nthr - 1) / nthr;
        const int beg = tid * chunk;
        const int end = min(beg + chunk, L);

        // per-thread separator count (int4 fast path when aligned)
        int c = 0;
        if (((chunk & 3) == 0) && ((L & 3) == 0) && (beg < end)) {
            const int4* m4 = (const int4*)(mrow + beg);
            const int n4 = (end - beg) >> 2;
            for (int i = 0; i < n4; ++i) {
                int4 v = m4[i];
                c += (v.x != 0) + (v.y != 0) + (v.z != 0) + (v.w != 0);
            }
        } else {
            for (int i = beg; i < end; ++i) c += (mrow[i] != 0);
        }

        // warp inclusive scan
        int inc = c;
        #pragma unroll
        for (int o = 1; o < 32; o <<= 1) {
            int v = __shfl_up_sync(0xffffffffu, inc, o);
            if (lane >= o) inc += v;
        }
        if (lane == 31) sh_warp[wid] = inc;
        __syncthreads();

        if (tid == 0) {
            int acc = 0;
            #pragma unroll
            for (int w = 0; w < 8; ++w) { int t = sh_warp[w]; sh_warp[w] = acc; acc += t; }
            sh_warp[8] = acc;
        }
        __syncthreads();

        const int excl = inc - c + sh_warp[wid];
        const int nsep = sh_warp[8];

        int j = excl;
        for (int i = beg; i < end; ++i) {
            if (mrow[i] != 0) {
                if (j < MAX_SEPS_CAP) sh_sep[j] = i;
                ++j;
            }
        }
        __syncthreads();

        for (int s = tid; s < max_ingr; s += nthr) {
            int start, cnt;
            if (s < nsep) {
                start = (s == 0) ? 0 : (sh_sep[s - 1] + 1);
                cnt   = sh_sep[s] - start;
            } else if (s == nsep) {
                start = (nsep == 0) ? 0 : (sh_sep[nsep - 1] + 1);
                cnt   = L - start;
            } else {
                start = 0;
                cnt   = 0;
            }
            meta[b * max_ingr + s] = make_int4(b * L + start, cnt, s, 0);
        }
        __syncthreads();
    }
}

// ---------------------------------------------------------------------------
// Kernel 2 (fast path, D % 4 == 0): one warp per row, single accumulator,
// 5-deep float4 loads, forced 6 blocks/SM.
// ---------------------------------------------------------------------------
__global__ void __launch_bounds__(256, 6)
seg_mean_v4_kernel(const float4* __restrict__ x4,
                   const float4* __restrict__ pe4,
                   const int4* __restrict__ meta,
                   float4* __restrict__ out4,
                   int D4, int OUT_ROWS)
{
    __shared__ int4 sh_meta[ROWS_PER_BLOCK];

    const int base = blockIdx.x * ROWS_PER_BLOCK;
    const int tid  = threadIdx.x;
    if (tid < ROWS_PER_BLOCK && base + tid < OUT_ROWS)
        sh_meta[tid] = meta[base + tid];
    __syncthreads();

    const int lane = tid & 31;
    const int w    = tid >> 5;

    const int r = base + w;
    if (r >= OUT_ROWS) return;

    const int4 md  = sh_meta[w];
    const int start = md.x;
    const int cnt   = md.y;
    const int s     = md.z;

    const float inv = (cnt > 0) ? (1.0f / (float)cnt) : 0.0f;

    for (int c = lane; c < D4; c += 32) {
        const float4* __restrict__ xp = x4 + start * D4 + c;
        float4 acc = {0.f, 0.f, 0.f, 0.f};
        int t = 0;
        // 5-deep unroll: cnt=15 -> exactly 3 iterations, no tail
        for (; t + 5 <= cnt; t += 5) {
            float4 v0 = xp[0];
            float4 v1 = xp[D4];
            float4 v2 = xp[2 * D4];
            float4 v3 = xp[3 * D4];
            float4 v4 = xp[4 * D4];
            xp += 5 * D4;
            acc.x += ((v0.x + v1.x) + (v2.x + v3.x)) + v4.x;
            acc.y += ((v0.y + v1.y) + (v2.y + v3.y)) + v4.y;
            acc.z += ((v0.z + v1.z) + (v2.z + v3.z)) + v4.z;
            acc.w += ((v0.w + v1.w) + (v2.w + v3.w)) + v4.w;
        }
        for (; t < cnt; ++t) {
            float4 v = xp[0];
            xp += D4;
            acc.x += v.x; acc.y += v.y; acc.z += v.z; acc.w += v.w;
        }

        float4 p = pe4[s * D4 + c];
        float4 o;
        o.x = acc.x * inv + p.x;
        o.y = acc.y * inv + p.y;
        o.z = acc.z * inv + p.z;
        o.w = acc.w * inv + p.w;
        out4[r * D4 + c] = o;
    }
}

// ---------------------------------------------------------------------------
// Kernel 2 (generic fallback, any D): one block per row, thread = channel.
// ---------------------------------------------------------------------------
__global__ void seg_mean_scalar_kernel(const float* __restrict__ x,
                                       const float* __restrict__ pe,
                                       const int4* __restrict__ meta,
                                       float* __restrict__ out,
                                       int D)
{
    const int r = blockIdx.x;
    const int4 md = meta[r];
    const int start = md.x;
    const int cnt   = md.y;
    const int s     = md.z;
    const float inv = (cnt > 0) ? (1.0f / (float)cnt) : 0.0f;

    for (int d = threadIdx.x; d < D; d += blockDim.x) {
        const float* xp = x + (long long)start * D + d;
        float a0 = 0.f, a1 = 0.f, a2 = 0.f, a3 = 0.f;
        int t = 0;
        for (; t + 4 <= cnt; t += 4) {
            a0 += xp[(long long)(t + 0) * D];
            a1 += xp[(long long)(t + 1) * D];
            a2 += xp[(long long)(t + 2) * D];
            a3 += xp[(long long)(t + 3) * D];
        }
        for (; t < cnt; ++t) a0 += xp[(long long)t * D];
        float sum = (a0 + a1) + (a2 + a3);
        out[(long long)r * D + d] = sum * inv + pe[(long long)s * D + d];
    }
}

// ---------------------------------------------------------------------------
// Launch
// ---------------------------------------------------------------------------
extern "C" void kernel_launch(void* const* d_in, const int* in_sizes, int n_in,
                              void* d_out, int out_size)
{
    const float* x    = (const float*)d_in[0];
    const int*   mask = (const int*)d_in[1];
    const float* pe   = (const float*)d_in[2];

    const int* max_ingr_ptr;
    if (n_in >= 4) {
        max_ingr_ptr = (const int*)d_in[3];
    } else {
        int* p = nullptr;
        cudaGetSymbolAddress((void**)&p, g_fallback_max_ingr);
        max_ingr_ptr = p;
    }

    const int x_size    = in_sizes[0];            // B*L*D
    const int mask_size = in_sizes[1];            // B*L
    const int D         = x_size / mask_size;     // 128
    const int OUT_ROWS  = out_size / D;           // B*max_ingr

    int4* meta_p = nullptr;
    cudaGetSymbolAddress((void**)&meta_p, g_seg_meta);

    // Kernel 1: grid-stride over batch rows (B resolved on-device).
    seg_bounds_kernel<<<256, 256>>>(mask, max_ingr_ptr,
                                    mask_size, OUT_ROWS, meta_p);

    if ((D & 3) == 0) {
        const int D4 = D >> 2;
        const int grid = (OUT_ROWS + ROWS_PER_BLOCK - 1) / ROWS_PER_BLOCK;
        seg_mean_v4_kernel<<<grid, 256>>>(
            (const float4*)x, (const float4*)pe, meta_p,
            (float4*)d_out, D4, OUT_ROWS);
    } else {
        seg_mean_scalar_kernel<<<OUT_ROWS, 128>>>(
            x, pe, meta_p, (float*)d_out, D);
    }
}